// round 1
// baseline (speedup 1.0000x reference)
#include <cuda_runtime.h>
#include <math.h>

// Problem constants
#define SB   2048          // sequence length
#define BB   2             // batch
#define DD   1024          // model dim
#define NH   16            // heads
#define HDIM 64            // head dim
#define MR   (BB*SB)       // 4096 rows

// Scratch (device globals: no allocation allowed in kernel_launch)
__device__ float g_q[(size_t)BB*NH*SB*HDIM];   // [b,h,s,hd]
__device__ float g_k[(size_t)BB*NH*SB*HDIM];
__device__ float g_v[(size_t)BB*NH*SB*HDIM];
__device__ float g_ctx[(size_t)MR*DD];         // [b,s,d]

// ---------------------------------------------------------------------------
// Fused QKV projection: [4096,1024] x [1024,1024]^T for each of Wq,Wk,Wv.
// Classic 128x128x8 SGEMM, 256 threads, 8x8 per thread (2x2 blocks of 4x4).
// Writes directly into head-transposed [b,h,s,hd] layout.
// ---------------------------------------------------------------------------
__global__ __launch_bounds__(256) void qkv_gemm(
    const float* __restrict__ X,
    const float* __restrict__ Wq,
    const float* __restrict__ Wk,
    const float* __restrict__ Wv)
{
    __shared__ float As[8][132];
    __shared__ float Bs[8][132];

    const int n0    = blockIdx.x * 128;     // 0..3071 (concat of q/k/v cols)
    const int m0    = blockIdx.y * 128;
    const int which = n0 >> 10;             // 0=q,1=k,2=v (128 | 1024)
    const int nb    = n0 & 1023;

    const float* __restrict__ W   = (which == 0) ? Wq : (which == 1 ? Wk : Wv);
    float*       __restrict__ OUT = (which == 0) ? g_q : (which == 1 ? g_k : g_v);

    const int tid = threadIdx.x;
    const int tx  = tid & 15, ty = tid >> 4;
    const int lr  = tid >> 1;               // 0..127 (load row)
    const int lc  = (tid & 1) << 2;         // 0 or 4 (load col segment)

    float acc[2][2][4][4];
    #pragma unroll
    for (int p = 0; p < 2; p++)
        #pragma unroll
        for (int q = 0; q < 2; q++)
            #pragma unroll
            for (int i = 0; i < 4; i++)
                #pragma unroll
                for (int j = 0; j < 4; j++)
                    acc[p][q][i][j] = 0.0f;

    const float* xrow = X + (size_t)(m0 + lr) * DD + lc;
    const float* wrow = W + (size_t)(nb + lr) * DD + lc;

    for (int k0 = 0; k0 < DD; k0 += 8) {
        float4 av = *(const float4*)(xrow + k0);
        float4 bv = *(const float4*)(wrow + k0);
        As[lc+0][lr] = av.x; As[lc+1][lr] = av.y; As[lc+2][lr] = av.z; As[lc+3][lr] = av.w;
        Bs[lc+0][lr] = bv.x; Bs[lc+1][lr] = bv.y; Bs[lc+2][lr] = bv.z; Bs[lc+3][lr] = bv.w;
        __syncthreads();
        #pragma unroll
        for (int k = 0; k < 8; k++) {
            float a[2][4], b[2][4];
            *(float4*)a[0] = *(const float4*)&As[k][ty*4];
            *(float4*)a[1] = *(const float4*)&As[k][ty*4 + 64];
            *(float4*)b[0] = *(const float4*)&Bs[k][tx*4];
            *(float4*)b[1] = *(const float4*)&Bs[k][tx*4 + 64];
            #pragma unroll
            for (int p = 0; p < 2; p++)
                #pragma unroll
                for (int q = 0; q < 2; q++)
                    #pragma unroll
                    for (int i = 0; i < 4; i++)
                        #pragma unroll
                        for (int j = 0; j < 4; j++)
                            acc[p][q][i][j] = fmaf(a[p][i], b[q][j], acc[p][q][i][j]);
        }
        __syncthreads();
    }

    #pragma unroll
    for (int p = 0; p < 2; p++) {
        #pragma unroll
        for (int i = 0; i < 4; i++) {
            int m = m0 + p*64 + ty*4 + i;
            int b = m >> 11;            // /2048
            int s = m & 2047;
            #pragma unroll
            for (int q = 0; q < 2; q++) {
                int cc = nb + q*64 + tx*4;     // col within [0,1024)
                int h  = cc >> 6;
                int hd = cc & 63;
                float4 v = make_float4(acc[p][q][i][0], acc[p][q][i][1],
                                       acc[p][q][i][2], acc[p][q][i][3]);
                *(float4*)&OUT[(((size_t)(b*NH + h))*SB + s)*HDIM + hd] = v;
            }
        }
    }
}

// ---------------------------------------------------------------------------
// Flash attention, causal, per (b,h) x 64-row q tile. 256 threads.
// Thread (ty,tx) owns rows {ty,ty+16,ty+32,ty+48}, cols {tx,tx+16,tx+32,tx+48}
// (stride-16 mapping -> conflict-free LDS with 65-float padded rows).
// ---------------------------------------------------------------------------
__global__ __launch_bounds__(256) void flash_attn()
{
    __shared__ float Qs[64][65];
    __shared__ float Ks[64][65];
    __shared__ float Vs[64][65];
    __shared__ float Ps[64][65];

    const int qt = blockIdx.x;        // q tile index 0..31
    const int bh = blockIdx.y;        // 0..31
    const int q0 = qt * 64;

    const float* __restrict__ Qp = g_q + ((size_t)bh*SB + q0)*HDIM;
    const float* __restrict__ Kp = g_k + (size_t)bh*SB*HDIM;
    const float* __restrict__ Vp = g_v + (size_t)bh*SB*HDIM;

    const int tid = threadIdx.x;
    const int tx = tid & 15, ty = tid >> 4;

    // Load Q tile (stays resident)
    for (int t = tid; t < 64*64; t += 256) {
        int r = t >> 6, d = t & 63;
        Qs[r][d] = Qp[t];
    }

    float m_i[4], l_i[4], o[4][4];
    #pragma unroll
    for (int i = 0; i < 4; i++) {
        m_i[i] = -INFINITY; l_i[i] = 0.0f;
        #pragma unroll
        for (int j = 0; j < 4; j++) o[i][j] = 0.0f;
    }

    for (int kt = 0; kt <= qt; kt++) {
        const int c0 = kt * 64;
        __syncthreads();  // protect Ks/Vs/Ps from previous iteration
        for (int t = tid; t < 64*64; t += 256) {
            int r = t >> 6, d = t & 63;
            Ks[r][d] = Kp[(size_t)(c0 + r)*HDIM + d];
            Vs[r][d] = Vp[(size_t)(c0 + r)*HDIM + d];
        }
        __syncthreads();

        // S = Q K^T (64x64x64)
        float s[4][4];
        #pragma unroll
        for (int i = 0; i < 4; i++)
            #pragma unroll
            for (int j = 0; j < 4; j++) s[i][j] = 0.0f;
        #pragma unroll 4
        for (int d = 0; d < 64; d++) {
            float qv[4], kv[4];
            #pragma unroll
            for (int i = 0; i < 4; i++) qv[i] = Qs[ty + 16*i][d];
            #pragma unroll
            for (int j = 0; j < 4; j++) kv[j] = Ks[tx + 16*j][d];
            #pragma unroll
            for (int i = 0; i < 4; i++)
                #pragma unroll
                for (int j = 0; j < 4; j++)
                    s[i][j] = fmaf(qv[i], kv[j], s[i][j]);
        }

        // scale + causal mask (only diagonal tile needs masking)
        const bool diag = (kt == qt);
        #pragma unroll
        for (int i = 0; i < 4; i++) {
            int r = ty + 16*i;
            #pragma unroll
            for (int j = 0; j < 4; j++) {
                int c = tx + 16*j;
                float sv = s[i][j] * 0.125f;   // 1/sqrt(64)
                if (diag && c > r) sv = -INFINITY;
                s[i][j] = sv;
            }
        }

        // online softmax
        float rm[4], rs[4], mn[4], al[4];
        #pragma unroll
        for (int i = 0; i < 4; i++) {
            rm[i] = fmaxf(fmaxf(s[i][0], s[i][1]), fmaxf(s[i][2], s[i][3]));
        }
        #pragma unroll
        for (int msk = 8; msk >= 1; msk >>= 1)
            #pragma unroll
            for (int i = 0; i < 4; i++)
                rm[i] = fmaxf(rm[i], __shfl_xor_sync(0xffffffffu, rm[i], msk));
        #pragma unroll
        for (int i = 0; i < 4; i++) {
            mn[i] = fmaxf(m_i[i], rm[i]);
            al[i] = __expf(m_i[i] - mn[i]);
            rs[i] = 0.0f;
            #pragma unroll
            for (int j = 0; j < 4; j++) {
                s[i][j] = __expf(s[i][j] - mn[i]);   // s becomes P
                rs[i] += s[i][j];
            }
        }
        #pragma unroll
        for (int msk = 8; msk >= 1; msk >>= 1)
            #pragma unroll
            for (int i = 0; i < 4; i++)
                rs[i] += __shfl_xor_sync(0xffffffffu, rs[i], msk);
        #pragma unroll
        for (int i = 0; i < 4; i++) {
            l_i[i] = l_i[i] * al[i] + rs[i];
            m_i[i] = mn[i];
            #pragma unroll
            for (int j = 0; j < 4; j++) {
                o[i][j] *= al[i];
                Ps[ty + 16*i][tx + 16*j] = s[i][j];
            }
        }
        __syncthreads();

        // O += P V (64x64x64)
        #pragma unroll 4
        for (int c = 0; c < 64; c++) {
            float pv[4], vv[4];
            #pragma unroll
            for (int i = 0; i < 4; i++) pv[i] = Ps[ty + 16*i][c];
            #pragma unroll
            for (int j = 0; j < 4; j++) vv[j] = Vs[c][tx + 16*j];
            #pragma unroll
            for (int i = 0; i < 4; i++)
                #pragma unroll
                for (int j = 0; j < 4; j++)
                    o[i][j] = fmaf(pv[i], vv[j], o[i][j]);
        }
    }

    // finalize + write ctx in [b,s,d] layout
    const int b = bh / NH, h = bh % NH;
    #pragma unroll
    for (int i = 0; i < 4; i++) {
        int r = ty + 16*i;
        float inv = 1.0f / l_i[i];
        #pragma unroll
        for (int j = 0; j < 4; j++) {
            int dd = tx + 16*j;
            g_ctx[((size_t)(b*SB + q0 + r))*DD + h*HDIM + dd] = o[i][j] * inv;
        }
    }
}

// ---------------------------------------------------------------------------
// Output projection: ctx [4096,1024] @ Wo^T + bo -> out [4096,1024]
// ---------------------------------------------------------------------------
__global__ __launch_bounds__(256) void out_gemm(
    const float* __restrict__ Wo,
    const float* __restrict__ bo,
    float* __restrict__ OUT)
{
    __shared__ float As[8][132];
    __shared__ float Bs[8][132];

    const int n0 = blockIdx.x * 128;
    const int m0 = blockIdx.y * 128;

    const int tid = threadIdx.x;
    const int tx  = tid & 15, ty = tid >> 4;
    const int lr  = tid >> 1;
    const int lc  = (tid & 1) << 2;

    float acc[2][2][4][4];
    #pragma unroll
    for (int p = 0; p < 2; p++)
        #pragma unroll
        for (int q = 0; q < 2; q++)
            #pragma unroll
            for (int i = 0; i < 4; i++)
                #pragma unroll
                for (int j = 0; j < 4; j++)
                    acc[p][q][i][j] = 0.0f;

    const float* arow = g_ctx + (size_t)(m0 + lr) * DD + lc;
    const float* wrow = Wo    + (size_t)(n0 + lr) * DD + lc;

    for (int k0 = 0; k0 < DD; k0 += 8) {
        float4 av = *(const float4*)(arow + k0);
        float4 bv = *(const float4*)(wrow + k0);
        As[lc+0][lr] = av.x; As[lc+1][lr] = av.y; As[lc+2][lr] = av.z; As[lc+3][lr] = av.w;
        Bs[lc+0][lr] = bv.x; Bs[lc+1][lr] = bv.y; Bs[lc+2][lr] = bv.z; Bs[lc+3][lr] = bv.w;
        __syncthreads();
        #pragma unroll
        for (int k = 0; k < 8; k++) {
            float a[2][4], b[2][4];
            *(float4*)a[0] = *(const float4*)&As[k][ty*4];
            *(float4*)a[1] = *(const float4*)&As[k][ty*4 + 64];
            *(float4*)b[0] = *(const float4*)&Bs[k][tx*4];
            *(float4*)b[1] = *(const float4*)&Bs[k][tx*4 + 64];
            #pragma unroll
            for (int p = 0; p < 2; p++)
                #pragma unroll
                for (int q = 0; q < 2; q++)
                    #pragma unroll
                    for (int i = 0; i < 4; i++)
                        #pragma unroll
                        for (int j = 0; j < 4; j++)
                            acc[p][q][i][j] = fmaf(a[p][i], b[q][j], acc[p][q][i][j]);
        }
        __syncthreads();
    }

    #pragma unroll
    for (int p = 0; p < 2; p++) {
        #pragma unroll
        for (int i = 0; i < 4; i++) {
            int m = m0 + p*64 + ty*4 + i;
            #pragma unroll
            for (int q = 0; q < 2; q++) {
                int n = n0 + q*64 + tx*4;
                float4 bb = *(const float4*)&bo[n];
                float4 v = make_float4(acc[p][q][i][0] + bb.x,
                                       acc[p][q][i][1] + bb.y,
                                       acc[p][q][i][2] + bb.z,
                                       acc[p][q][i][3] + bb.w);
                *(float4*)&OUT[(size_t)m*DD + n] = v;
            }
        }
    }
}

// ---------------------------------------------------------------------------
extern "C" void kernel_launch(void* const* d_in, const int* in_sizes, int n_in,
                              void* d_out, int out_size)
{
    const float* x  = (const float*)d_in[0];
    const float* Wq = (const float*)d_in[1];
    const float* Wk = (const float*)d_in[2];
    const float* Wv = (const float*)d_in[3];
    const float* Wo = (const float*)d_in[4];
    const float* bo = (const float*)d_in[5];
    float* out = (float*)d_out;

    qkv_gemm<<<dim3(3072/128, MR/128), 256>>>(x, Wq, Wk, Wv);
    flash_attn<<<dim3(SB/64, BB*NH), 256>>>();
    out_gemm<<<dim3(DD/128, MR/128), 256>>>(Wo, bo, out);
}